// round 3
// baseline (speedup 1.0000x reference)
#include <cuda_runtime.h>

namespace {

constexpr int kS  = 2048;
constexpr int kD  = 64;
constexpr int kBH = 64;
constexpr int TQ  = 256;   // query rows per CTA
constexpr int TK  = 64;    // key cols per tile
constexpr int NT  = 256;
constexpr int KTST = 68;   // Kt row stride (floats)
constexpr int VST  = 68;   // Vp row stride
constexpr long long OUT_ELEMS = (long long)kBH * kS * kD;  // attn starts after
constexpr float SCALE = 0.125f;

__device__ __forceinline__ void fma2(unsigned long long &d,
                                     unsigned long long a,
                                     unsigned long long b) {
  asm("fma.rn.f32x2 %0, %1, %2, %3;" : "=l"(d) : "l"(a), "l"(b), "l"(d));
}
__device__ __forceinline__ float2 u2f(unsigned long long v) {
  float2 r;
  asm("mov.b64 {%0, %1}, %2;" : "=f"(r.x), "=f"(r.y) : "l"(v));
  return r;
}
// duplicate scalar into both f32x2 lanes (ALU pipe, not LDS)
__device__ __forceinline__ unsigned long long pk(float x) {
  unsigned long long r;
  asm("mov.b64 %0, {%1, %1};" : "=l"(r) : "f"(x));
  return r;
}

}  // namespace

extern "C" __global__ void __launch_bounds__(NT, 1)
sdpa_kernel(const float *__restrict__ Q, const float *__restrict__ K,
            const float *__restrict__ V, const int *__restrict__ M,
            float *__restrict__ Out) {
  extern __shared__ float sm[];
  float *Qs   = sm;                  // [256][64]  column-rotated by 8*(h&3)
  float *Kt   = Qs + TQ * kD;        // [64 d][68] key-permuted d-major
  float *Vp   = Kt + kD * KTST;      // [64 key][68] d-permuted
  float *Es   = Vp + TK * VST;       // [256][64]  column-rotated by 8*(h&3)
  float *invS = Es + TQ * kD;        // [256]
  int   *mS   = (int *)(invS + TQ);  // [64]

  const int tid = threadIdx.x;
  const int g   = tid & 7;    // 8-wide group: keys (QK) / d (PV)
  const int h   = tid >> 3;   // row group 0..31
  const int r0  = h * 8;
  const int rot = (h & 3) * 8;  // smem column rotation for Qs/Es
  const int bh  = blockIdx.y;
  const int q0  = blockIdx.x * TQ;

  const float *Qg = Q + ((size_t)bh * kS + q0) * kD;
  const float *Kg = K + (size_t)bh * kS * kD;
  const float *Vg = V + (size_t)bh * kS * kD;
  const int   *Mg = M + (size_t)bh * kS;
  float *Og = Out + ((size_t)bh * kS + q0) * kD;
  float *Ag = Out + OUT_ELEMS + ((size_t)bh * kS + q0) * (size_t)kS;

  // ---- load Q tile once, rotated columns per 8-row group ----
  for (int f = tid; f < TQ * kD / 4; f += NT) {
    int row = f >> 4, c4 = (f & 15) << 2;
    int col = (c4 + ((row >> 3) & 3) * 8) & 63;
    *(float4 *)&Qs[row * kD + col] = *(const float4 *)&Qg[row * kD + c4];
  }

  unsigned long long Oa[8][4];  // [row][d-pair] f32x2 accumulators
  float part[8];
#pragma unroll
  for (int i = 0; i < 8; i++) {
    Oa[i][0] = Oa[i][1] = Oa[i][2] = Oa[i][3] = 0ull;
    part[i] = 0.f;
  }

  for (int kt = 0; kt < kS / TK; kt++) {
    __syncthreads();  // prior tile's Es/Kt/Vp fully consumed

    // K tile -> Kt[d][pos(key)]: pos = c*32 + (key/8)*4 + key%4, c=(key%8)/4
    const float *Ktg = Kg + (size_t)kt * TK * kD;
#pragma unroll 1
    for (int f = tid; f < TK * 16; f += NT) {
      int key = f & 63, dq = (f >> 6) << 2;
      float4 kv = *(const float4 *)&Ktg[key * kD + dq];
      int pos = ((key & 4) << 3) + ((key >> 3) << 2) + (key & 3);
      Kt[(dq + 0) * KTST + pos] = kv.x;
      Kt[(dq + 1) * KTST + pos] = kv.y;
      Kt[(dq + 2) * KTST + pos] = kv.z;
      Kt[(dq + 3) * KTST + pos] = kv.w;
    }
    // V tile -> Vp[key][pos(d)] (float4 stays contiguous under pos)
    const float *Vtg = Vg + (size_t)kt * TK * kD;
#pragma unroll 1
    for (int f = tid; f < TK * 16; f += NT) {
      int key = f >> 4, d4 = (f & 15) << 2;
      float4 vv = *(const float4 *)&Vtg[key * kD + d4];
      int pos = ((d4 & 4) << 3) + ((d4 >> 3) << 2);
      *(float4 *)&Vp[key * VST + pos] = vv;
    }
    if (tid < TK) mS[tid] = Mg[kt * TK + tid];
    __syncthreads();

    // ---- QK^T: 8 rows x 8 keys, acc packs key pairs ----
    unsigned long long acc[8][4];
#pragma unroll
    for (int i = 0; i < 8; i++)
      acc[i][0] = acc[i][1] = acc[i][2] = acc[i][3] = 0ull;

#pragma unroll 1
    for (int d4 = 0; d4 < kD; d4 += 4) {
      ulonglong2 kA[4], kB[4];
#pragma unroll
      for (int j = 0; j < 4; j++) {
        kA[j] = *(const ulonglong2 *)&Kt[(d4 + j) * KTST + g * 4];
        kB[j] = *(const ulonglong2 *)&Kt[(d4 + j) * KTST + 32 + g * 4];
      }
      const int qoff = (d4 + rot) & 63;
#pragma unroll
      for (int i = 0; i < 8; i++) {
        float4 q4 = *(const float4 *)&Qs[(r0 + i) * kD + qoff];
        unsigned long long qq;
        qq = pk(q4.x);
        fma2(acc[i][0], qq, kA[0].x); fma2(acc[i][1], qq, kA[0].y);
        fma2(acc[i][2], qq, kB[0].x); fma2(acc[i][3], qq, kB[0].y);
        qq = pk(q4.y);
        fma2(acc[i][0], qq, kA[1].x); fma2(acc[i][1], qq, kA[1].y);
        fma2(acc[i][2], qq, kB[1].x); fma2(acc[i][3], qq, kB[1].y);
        qq = pk(q4.z);
        fma2(acc[i][0], qq, kA[2].x); fma2(acc[i][1], qq, kA[2].y);
        fma2(acc[i][2], qq, kB[2].x); fma2(acc[i][3], qq, kB[2].y);
        qq = pk(q4.w);
        fma2(acc[i][0], qq, kA[3].x); fma2(acc[i][1], qq, kA[3].y);
        fma2(acc[i][2], qq, kB[3].x); fma2(acc[i][3], qq, kB[3].y);
      }
    }

    // ---- mask + exp; write Es (smem, rotated) + attn (global, from regs) ----
    const int4 mA = *(const int4 *)&mS[g * 8];
    const int4 mB = *(const int4 *)&mS[g * 8 + 4];
    const int ecol = ((g * 8) + rot) & 63;
    float *Agt = Ag + kt * TK + g * 8;
#pragma unroll
    for (int i = 0; i < 8; i++) {
      float2 p0 = u2f(acc[i][0]), p1 = u2f(acc[i][1]);
      float2 p2 = u2f(acc[i][2]), p3 = u2f(acc[i][3]);
      float4 eL, eH;
      eL.x = mA.x ? __expf(p0.x * SCALE) : 0.f;
      eL.y = mA.y ? __expf(p0.y * SCALE) : 0.f;
      eL.z = mA.z ? __expf(p1.x * SCALE) : 0.f;
      eL.w = mA.w ? __expf(p1.y * SCALE) : 0.f;
      eH.x = mB.x ? __expf(p2.x * SCALE) : 0.f;
      eH.y = mB.y ? __expf(p2.y * SCALE) : 0.f;
      eH.z = mB.z ? __expf(p3.x * SCALE) : 0.f;
      eH.w = mB.w ? __expf(p3.y * SCALE) : 0.f;
      part[i] += (eL.x + eL.y + eL.z + eL.w) + (eH.x + eH.y + eH.z + eH.w);
      *(float4 *)&Es[(r0 + i) * kD + ecol] = eL;
      *(float4 *)&Es[(r0 + i) * kD + ((ecol + 4) & 63)] = eH;
      *(float4 *)&Agt[(size_t)(r0 + i) * kS] = eL;
      *(float4 *)&Agt[(size_t)(r0 + i) * kS + 4] = eH;
    }
    __syncthreads();  // Es visible to all

    // ---- PV: 8 rows x 8 d, acc packs d pairs ----
#pragma unroll 1
    for (int c4 = 0; c4 < TK; c4 += 4) {
      ulonglong2 vA[4], vB[4];
#pragma unroll
      for (int j = 0; j < 4; j++) {
        vA[j] = *(const ulonglong2 *)&Vp[(c4 + j) * VST + g * 4];
        vB[j] = *(const ulonglong2 *)&Vp[(c4 + j) * VST + 32 + g * 4];
      }
      const int eoff = (c4 + rot) & 63;
#pragma unroll
      for (int i = 0; i < 8; i++) {
        float4 e4 = *(const float4 *)&Es[(r0 + i) * kD + eoff];
        unsigned long long ee;
        ee = pk(e4.x);
        fma2(Oa[i][0], ee, vA[0].x); fma2(Oa[i][1], ee, vA[0].y);
        fma2(Oa[i][2], ee, vB[0].x); fma2(Oa[i][3], ee, vB[0].y);
        ee = pk(e4.y);
        fma2(Oa[i][0], ee, vA[1].x); fma2(Oa[i][1], ee, vA[1].y);
        fma2(Oa[i][2], ee, vB[1].x); fma2(Oa[i][3], ee, vB[1].y);
        ee = pk(e4.z);
        fma2(Oa[i][0], ee, vA[2].x); fma2(Oa[i][1], ee, vA[2].y);
        fma2(Oa[i][2], ee, vB[2].x); fma2(Oa[i][3], ee, vB[2].y);
        ee = pk(e4.w);
        fma2(Oa[i][0], ee, vA[3].x); fma2(Oa[i][1], ee, vA[3].y);
        fma2(Oa[i][2], ee, vB[3].x); fma2(Oa[i][3], ee, vB[3].y);
      }
    }
  }

  // ---- finalize: reduce row sums over the 8 g-lanes, write O ----
#pragma unroll
  for (int i = 0; i < 8; i++) {
    float s = part[i];
    s += __shfl_xor_sync(0xffffffffu, s, 1);
    s += __shfl_xor_sync(0xffffffffu, s, 2);
    s += __shfl_xor_sync(0xffffffffu, s, 4);
    float inv = 1.0f / s;
    float2 o0 = u2f(Oa[i][0]), o1 = u2f(Oa[i][1]);
    float2 o2 = u2f(Oa[i][2]), o3 = u2f(Oa[i][3]);
    float4 wL = {o0.x * inv, o0.y * inv, o1.x * inv, o1.y * inv};
    float4 wH = {o2.x * inv, o2.y * inv, o3.x * inv, o3.y * inv};
    *(float4 *)&Og[(r0 + i) * kD + g * 8]     = wL;
    *(float4 *)&Og[(r0 + i) * kD + g * 8 + 4] = wH;
    if (g == 0) invS[r0 + i] = inv;
  }
  __syncthreads();

  // ---- phase 2: rescale this block's attn rows ----
#pragma unroll 1
  for (int f = tid; f < TQ * (kS / 4); f += NT) {
    int row = f >> 9;
    int c4  = (f & 511) << 2;
    float4 p = *(float4 *)&Ag[(size_t)row * kS + c4];
    float iv = invS[row];
    p.x *= iv; p.y *= iv; p.z *= iv; p.w *= iv;
    *(float4 *)&Ag[(size_t)row * kS + c4] = p;
  }
}

extern "C" void kernel_launch(void *const *d_in, const int *in_sizes, int n_in,
                              void *d_out, int out_size) {
  const float *q = (const float *)d_in[0];
  const float *k = (const float *)d_in[1];
  const float *v = (const float *)d_in[2];
  const int   *m = (const int *)d_in[3];
  float *out = (float *)d_out;

  const size_t smem_bytes =
      (size_t)(TQ * kD + kD * KTST + TK * VST + TQ * kD + TQ) * sizeof(float) +
      (size_t)TK * sizeof(int);

  cudaFuncSetAttribute(sdpa_kernel, cudaFuncAttributeMaxDynamicSharedMemorySize,
                       (int)smem_bytes);

  dim3 grid(kS / TQ, kBH);  // (8, 64)
  sdpa_kernel<<<grid, NT, smem_bytes>>>(q, k, v, m, out);
}

// round 5
// speedup vs baseline: 1.5922x; 1.5922x over previous
#include <cuda_runtime.h>
#include <cuda_bf16.h>
#include <stdint.h>

namespace {

constexpr int kS = 2048, kD = 64;
constexpr long long OUT_ELEMS = 64LL * 2048 * 64;  // attn follows output
constexpr int TQ = 64, TK = 64, NT = 128, NTILES = kS / TK;
constexpr float SCALE = 0.125f;

// smem byte offsets
constexpr int OFF_INV  = 0;     // 64 floats
constexpr int OFF_MASK = 256;   // 2 u32
constexpr int OFF_QH = 512;
constexpr int OFF_QL = OFF_QH + 8192;
constexpr int OFF_KH = OFF_QL + 8192;
constexpr int OFF_KL = OFF_KH + 8192;
constexpr int OFF_VH = OFF_KL + 8192;   // Vt[d][key]
constexpr int OFF_VL = OFF_VH + 8192;
constexpr int OFF_PH = OFF_VL + 8192;
constexpr int OFF_PL = OFF_PH + 8192;
constexpr int SMEM_BYTES = OFF_PL + 8192;  // 66048

__device__ __forceinline__ uint32_t swz(uint32_t off) {
  return off ^ ((off >> 3) & 0x70);
}
__device__ __forceinline__ uint32_t s2u(const void *p) {
  uint32_t a;
  asm("{ .reg .u64 t; cvta.to.shared.u64 t, %1; cvt.u32.u64 %0, t; }"
      : "=r"(a) : "l"(p));
  return a;
}
// pack (lo, hi) floats -> bf16x2 (lo in low 16 bits)
__device__ __forceinline__ uint32_t pkbf(float lo, float hi) {
  uint32_t r;
  asm("cvt.rn.bf16x2.f32 %0, %1, %2;" : "=r"(r) : "f"(hi), "f"(lo));
  return r;
}
// split (a,b) -> hi bf16x2 + residual bf16x2
__device__ __forceinline__ void splitpair(float a, float b, uint32_t &h,
                                          uint32_t &l) {
  float ah = __bfloat162float(__float2bfloat16(a));
  float bh = __bfloat162float(__float2bfloat16(b));
  h = pkbf(ah, bh);
  l = pkbf(a - ah, b - bh);
}
__device__ __forceinline__ float2 upk2(uint32_t h, uint32_t l) {
  __nv_bfloat162 hb = *reinterpret_cast<__nv_bfloat162 *>(&h);
  __nv_bfloat162 lb = *reinterpret_cast<__nv_bfloat162 *>(&l);
  float2 hf = __bfloat1622float2(hb), lf = __bfloat1622float2(lb);
  return {hf.x + lf.x, hf.y + lf.y};
}
__device__ __forceinline__ void ldsm4(uint32_t *r, uint32_t addr) {
  asm volatile(
      "ldmatrix.sync.aligned.m8n8.x4.shared.b16 {%0,%1,%2,%3}, [%4];"
      : "=r"(r[0]), "=r"(r[1]), "=r"(r[2]), "=r"(r[3]) : "r"(addr));
}
__device__ __forceinline__ void mma16816(float *d, const uint32_t *a,
                                         uint32_t b0, uint32_t b1) {
  asm volatile(
      "mma.sync.aligned.m16n8k16.row.col.f32.bf16.bf16.f32 "
      "{%0,%1,%2,%3}, {%4,%5,%6,%7}, {%8,%9}, {%0,%1,%2,%3};"
      : "+f"(d[0]), "+f"(d[1]), "+f"(d[2]), "+f"(d[3])
      : "r"(a[0]), "r"(a[1]), "r"(a[2]), "r"(a[3]), "r"(b0), "r"(b1));
}

}  // namespace

extern "C" __global__ void __launch_bounds__(NT, 3)
sdpa_hmma(const float *__restrict__ Q, const float *__restrict__ K,
          const float *__restrict__ V, const int *__restrict__ M,
          float *__restrict__ Out) {
  extern __shared__ char smc[];
  const uint32_t sb = s2u(smc);
  const int tid = threadIdx.x;
  const int wid = tid >> 5, lid = tid & 31;
  const int wrow = wid * 16;          // warp's 16 q-rows
  const int bh = blockIdx.y, q0 = blockIdx.x * TQ;

  const float *Qg = Q + ((size_t)bh * kS + q0) * kD;
  const float *Kg = K + (size_t)bh * kS * kD;
  const float *Vg = V + (size_t)bh * kS * kD;
  const int *Mg = M + (size_t)bh * kS;
  float *Og = Out + ((size_t)bh * kS + q0) * kD;
  float *Ag = Out + OUT_ELEMS + ((size_t)bh * kS + q0) * (size_t)kS;

  // ---- Q load + scale + split (once) ----
  for (int f = tid; f < TQ * 16; f += NT) {
    int row = f >> 4, c4 = (f & 15) << 2;
    float4 x = *(const float4 *)&Qg[row * kD + c4];
    x.x *= SCALE; x.y *= SCALE; x.z *= SCALE; x.w *= SCALE;
    uint2 h, l;
    splitpair(x.x, x.y, h.x, l.x);
    splitpair(x.z, x.w, h.y, l.y);
    uint32_t off = swz((uint32_t)(row * 128 + c4 * 2));
    *(uint2 *)(smc + OFF_QH + off) = h;
    *(uint2 *)(smc + OFF_QL + off) = l;
  }

  float O[8][4];
#pragma unroll
  for (int i = 0; i < 8; i++)
#pragma unroll
    for (int j = 0; j < 4; j++) O[i][j] = 0.f;
  float rs0 = 0.f, rs1 = 0.f;

  // ldmatrix lane pattern (shared by A and B chunk loads)
  const int lrow = lid & 15;
  const int lcol16 = (lid >> 4) << 4;   // 0 or 16 bytes

  for (int kt = 0; kt < NTILES; kt++) {
    __syncthreads();  // K/V/P consumed by all warps

    // ---- K tile split (rows=key, 128B bf16 rows) ----
    const float *Ktg = Kg + (size_t)kt * TK * kD;
    for (int f = tid; f < TK * 16; f += NT) {
      int row = f >> 4, c4 = (f & 15) << 2;
      float4 x = *(const float4 *)&Ktg[row * kD + c4];
      uint2 h, l;
      splitpair(x.x, x.y, h.x, l.x);
      splitpair(x.z, x.w, h.y, l.y);
      uint32_t off = swz((uint32_t)(row * 128 + c4 * 2));
      *(uint2 *)(smc + OFF_KH + off) = h;
      *(uint2 *)(smc + OFF_KL + off) = l;
    }
    // ---- V tile split + transpose: Vt[d][key] ----
    const float *Vtg = Vg + (size_t)kt * TK * kD;
    for (int f = tid; f < TK * 16; f += NT) {
      int key = f >> 4, d4 = (f & 15) << 2;
      float4 v = *(const float4 *)&Vtg[key * kD + d4];
      float vv[4] = {v.x, v.y, v.z, v.w};
#pragma unroll
      for (int j = 0; j < 4; j++) {
        __nv_bfloat16 hb = __float2bfloat16(vv[j]);
        uint32_t off = swz((uint32_t)((d4 + j) * 128 + key * 2));
        *(__nv_bfloat16 *)(smc + OFF_VH + off) = hb;
        *(__nv_bfloat16 *)(smc + OFF_VL + off) =
            __float2bfloat16(vv[j] - __bfloat162float(hb));
      }
    }
    // ---- mask ballot: warp0 -> keys 0-31, warp1 -> keys 32-63 ----
    {
      int mv = (tid < TK) ? Mg[kt * TK + tid] : 0;
      uint32_t w = __ballot_sync(0xffffffffu, mv != 0);
      if (lid == 0 && wid < 2) ((uint32_t *)(smc + OFF_MASK))[wid] = w;
    }
    __syncthreads();

    // ---- QK^T: acc[8 n-tiles][4] ----
    float acc[8][4];
#pragma unroll
    for (int i = 0; i < 8; i++)
#pragma unroll
      for (int j = 0; j < 4; j++) acc[i][j] = 0.f;

#pragma unroll
    for (int kc = 0; kc < 4; kc++) {
      uint32_t ah[4], al[4];
      uint32_t aoff = swz((uint32_t)((wrow + lrow) * 128 + kc * 32 + lcol16));
      ldsm4(ah, sb + OFF_QH + aoff);
      ldsm4(al, sb + OFF_QL + aoff);
#pragma unroll
      for (int ng = 0; ng < 4; ng++) {
        uint32_t bh4[4], bl4[4];
        uint32_t boff =
            swz((uint32_t)((ng * 16 + lrow) * 128 + kc * 32 + lcol16));
        ldsm4(bh4, sb + OFF_KH + boff);
        ldsm4(bl4, sb + OFF_KL + boff);
        mma16816(acc[ng * 2],     ah, bh4[0], bh4[2]);
        mma16816(acc[ng * 2 + 1], ah, bh4[1], bh4[3]);
        mma16816(acc[ng * 2],     ah, bl4[0], bl4[2]);
        mma16816(acc[ng * 2 + 1], ah, bl4[1], bl4[3]);
        mma16816(acc[ng * 2],     al, bh4[0], bh4[2]);
        mma16816(acc[ng * 2 + 1], al, bh4[1], bh4[3]);
      }
    }

    // ---- epilogue: mask + exp + rowsum + P split store ----
    const uint32_t mw0 = ((const uint32_t *)(smc + OFF_MASK))[0];
    const uint32_t mw1 = ((const uint32_t *)(smc + OFF_MASK))[1];
    const int prow = wrow + (lid >> 2);
#pragma unroll
    for (int nt = 0; nt < 8; nt++) {
      int c0 = nt * 8 + (lid & 3) * 2;
      uint32_t mword = (c0 < 32) ? mw0 : mw1;
      int bit = c0 & 31;
      bool m0 = (mword >> bit) & 1u, m1 = (mword >> (bit + 1)) & 1u;
      float e00 = m0 ? __expf(acc[nt][0]) : 0.f;
      float e01 = m1 ? __expf(acc[nt][1]) : 0.f;
      float e10 = m0 ? __expf(acc[nt][2]) : 0.f;
      float e11 = m1 ? __expf(acc[nt][3]) : 0.f;
      rs0 += e00 + e01;
      rs1 += e10 + e11;
      uint32_t h0, l0, h1, l1;
      splitpair(e00, e01, h0, l0);
      splitpair(e10, e11, h1, l1);
      uint32_t p0 = swz((uint32_t)(prow * 128 + nt * 16 + (lid & 3) * 4));
      uint32_t p1 = swz((uint32_t)((prow + 8) * 128 + nt * 16 + (lid & 3) * 4));
      *(uint32_t *)(smc + OFF_PH + p0) = h0;
      *(uint32_t *)(smc + OFF_PL + p0) = l0;
      *(uint32_t *)(smc + OFF_PH + p1) = h1;
      *(uint32_t *)(smc + OFF_PL + p1) = l1;
    }
    __syncthreads();  // P visible to all (attn write is cooperative)

    // ---- unnormalized attn write (coalesced, from P hi+lo) ----
    {
      int row = tid >> 1, half = tid & 1;
      float *dst = Ag + (size_t)row * kS + kt * TK + half * 32;
#pragma unroll
      for (int j = 0; j < 4; j++) {
        uint32_t off = swz((uint32_t)(row * 128 + half * 64 + j * 16));
        uint4 h = *(const uint4 *)(smc + OFF_PH + off);
        uint4 l = *(const uint4 *)(smc + OFF_PL + off);
        float2 a0 = upk2(h.x, l.x), a1 = upk2(h.y, l.y);
        float2 a2 = upk2(h.z, l.z), a3 = upk2(h.w, l.w);
        float4 o0 = {a0.x, a0.y, a1.x, a1.y};
        float4 o1 = {a2.x, a2.y, a3.x, a3.y};
        *(float4 *)(dst + j * 8) = o0;
        *(float4 *)(dst + j * 8 + 4) = o1;
      }
    }

    // ---- PV: O += P * Vt^T ----
#pragma unroll
    for (int kc = 0; kc < 4; kc++) {
      uint32_t ph[4], pl[4];
      uint32_t aoff = swz((uint32_t)((wrow + lrow) * 128 + kc * 32 + lcol16));
      ldsm4(ph, sb + OFF_PH + aoff);
      ldsm4(pl, sb + OFF_PL + aoff);
#pragma unroll
      for (int ng = 0; ng < 4; ng++) {
        uint32_t vh4[4], vl4[4];
        uint32_t boff =
            swz((uint32_t)((ng * 16 + lrow) * 128 + kc * 32 + lcol16));
        ldsm4(vh4, sb + OFF_VH + boff);
        ldsm4(vl4, sb + OFF_VL + boff);
        mma16816(O[ng * 2],     ph, vh4[0], vh4[2]);
        mma16816(O[ng * 2 + 1], ph, vh4[1], vh4[3]);
        mma16816(O[ng * 2],     ph, vl4[0], vl4[2]);
        mma16816(O[ng * 2 + 1], ph, vl4[1], vl4[3]);
        mma16816(O[ng * 2],     pl, vh4[0], vh4[2]);
        mma16816(O[ng * 2 + 1], pl, vh4[1], vh4[3]);
      }
    }
  }

  // ---- finalize: quad-reduce rowsums, write O, stash inv ----
  rs0 += __shfl_xor_sync(0xffffffffu, rs0, 1);
  rs0 += __shfl_xor_sync(0xffffffffu, rs0, 2);
  rs1 += __shfl_xor_sync(0xffffffffu, rs1, 1);
  rs1 += __shfl_xor_sync(0xffffffffu, rs1, 2);
  float inv0 = 1.0f / rs0, inv1 = 1.0f / rs1;
  const int r = wrow + (lid >> 2);
  if ((lid & 3) == 0) {
    ((float *)(smc + OFF_INV))[r] = inv0;
    ((float *)(smc + OFF_INV))[r + 8] = inv1;
  }
#pragma unroll
  for (int nt = 0; nt < 8; nt++) {
    int col = nt * 8 + (lid & 3) * 2;
    float2 w0 = {O[nt][0] * inv0, O[nt][1] * inv0};
    float2 w1 = {O[nt][2] * inv1, O[nt][3] * inv1};
    *(float2 *)&Og[(size_t)r * kD + col] = w0;
    *(float2 *)&Og[(size_t)(r + 8) * kD + col] = w1;
  }
  __syncthreads();

  // ---- phase 2: rescale this block's attn rows ----
  const float *invS = (const float *)(smc + OFF_INV);
#pragma unroll 1
  for (int f = tid; f < TQ * (kS / 4); f += NT) {
    int row = f >> 9;
    int c4 = (f & 511) << 2;
    float4 p = *(float4 *)&Ag[(size_t)row * kS + c4];
    float iv = invS[row];
    p.x *= iv; p.y *= iv; p.z *= iv; p.w *= iv;
    *(float4 *)&Ag[(size_t)row * kS + c4] = p;
  }
}

extern "C" void kernel_launch(void *const *d_in, const int *in_sizes, int n_in,
                              void *d_out, int out_size) {
  const float *q = (const float *)d_in[0];
  const float *k = (const float *)d_in[1];
  const float *v = (const float *)d_in[2];
  const int *m = (const int *)d_in[3];
  float *out = (float *)d_out;

  cudaFuncSetAttribute(sdpa_hmma, cudaFuncAttributeMaxDynamicSharedMemorySize,
                       SMEM_BYTES);
  dim3 grid(kS / TQ, 64);  // (32, 64), x-major keeps bh's K/V L2-hot
  sdpa_hmma<<<grid, NT, SMEM_BYTES>>>(q, k, v, m, out);
}

// round 6
// speedup vs baseline: 2.0476x; 1.2860x over previous
#include <cuda_runtime.h>
#include <cuda_bf16.h>
#include <stdint.h>

namespace {

constexpr int kS = 2048, kD = 64;
constexpr long long OUT_ELEMS = 64LL * 2048 * 64;  // attn follows output
constexpr int TQ = 64, TK = 64, NT = 128, NTILES = kS / TK;
constexpr float SCALE = 0.125f;

// smem byte offsets
constexpr int OFF_INV  = 0;     // 64 floats
constexpr int OFF_MASK = 256;   // 2 u32
constexpr int OFF_QH = 512;
constexpr int OFF_QL = OFF_QH + 8192;
constexpr int OFF_KH = OFF_QL + 8192;
constexpr int OFF_KL = OFF_KH + 8192;
constexpr int OFF_VH = OFF_KL + 8192;   // V[key][d] natural
constexpr int OFF_VL = OFF_VH + 8192;
constexpr int SMEM_BYTES = OFF_VL + 8192;  // 49664

__device__ __forceinline__ uint32_t swz(uint32_t off) {
  return off ^ ((off >> 3) & 0x70);
}
__device__ __forceinline__ uint32_t s2u(const void *p) {
  uint32_t a;
  asm("{ .reg .u64 t; cvta.to.shared.u64 t, %1; cvt.u32.u64 %0, t; }"
      : "=r"(a) : "l"(p));
  return a;
}
// pack (lo, hi) floats -> bf16x2 (lo in low 16 bits)
__device__ __forceinline__ uint32_t pkbf(float lo, float hi) {
  uint32_t r;
  asm("cvt.rn.bf16x2.f32 %0, %1, %2;" : "=r"(r) : "f"(hi), "f"(lo));
  return r;
}
// split (a,b) -> hi bf16x2 + residual bf16x2
__device__ __forceinline__ void splitpair(float a, float b, uint32_t &h,
                                          uint32_t &l) {
  float ah = __bfloat162float(__float2bfloat16(a));
  float bh = __bfloat162float(__float2bfloat16(b));
  h = pkbf(ah, bh);
  l = pkbf(a - ah, b - bh);
}
__device__ __forceinline__ void ldsm4(uint32_t *r, uint32_t addr) {
  asm volatile(
      "ldmatrix.sync.aligned.m8n8.x4.shared.b16 {%0,%1,%2,%3}, [%4];"
      : "=r"(r[0]), "=r"(r[1]), "=r"(r[2]), "=r"(r[3]) : "r"(addr));
}
__device__ __forceinline__ void ldsm4t(uint32_t *r, uint32_t addr) {
  asm volatile(
      "ldmatrix.sync.aligned.m8n8.x4.trans.shared.b16 {%0,%1,%2,%3}, [%4];"
      : "=r"(r[0]), "=r"(r[1]), "=r"(r[2]), "=r"(r[3]) : "r"(addr));
}
__device__ __forceinline__ void mma16816(float *d, const uint32_t *a,
                                         uint32_t b0, uint32_t b1) {
  asm volatile(
      "mma.sync.aligned.m16n8k16.row.col.f32.bf16.bf16.f32 "
      "{%0,%1,%2,%3}, {%4,%5,%6,%7}, {%8,%9}, {%0,%1,%2,%3};"
      : "+f"(d[0]), "+f"(d[1]), "+f"(d[2]), "+f"(d[3])
      : "r"(a[0]), "r"(a[1]), "r"(a[2]), "r"(a[3]), "r"(b0), "r"(b1));
}

}  // namespace

extern "C" __global__ void __launch_bounds__(NT, 3)
sdpa_hmma2(const float *__restrict__ Q, const float *__restrict__ K,
           const float *__restrict__ V, const int *__restrict__ M,
           float *__restrict__ Out) {
  extern __shared__ char smc[];
  const uint32_t sb = s2u(smc);
  const int tid = threadIdx.x;
  const int wid = tid >> 5, lid = tid & 31;
  const int wrow = wid * 16;          // warp's 16 q-rows
  const int bh = blockIdx.y, q0 = blockIdx.x * TQ;

  const float *Qg = Q + ((size_t)bh * kS + q0) * kD;
  const float *Kg = K + (size_t)bh * kS * kD;
  const float *Vg = V + (size_t)bh * kS * kD;
  const int *Mg = M + (size_t)bh * kS;
  float *Og = Out + ((size_t)bh * kS + q0) * kD;
  float *Ag = Out + OUT_ELEMS + ((size_t)bh * kS + q0) * (size_t)kS;

  // ---- Q load + scale + split into smem (once) ----
  for (int f = tid; f < TQ * 16; f += NT) {
    int row = f >> 4, c4 = (f & 15) << 2;
    float4 x = *(const float4 *)&Qg[row * kD + c4];
    x.x *= SCALE; x.y *= SCALE; x.z *= SCALE; x.w *= SCALE;
    uint2 h, l;
    splitpair(x.x, x.y, h.x, l.x);
    splitpair(x.z, x.w, h.y, l.y);
    uint32_t off = swz((uint32_t)(row * 128 + c4 * 2));
    *(uint2 *)(smc + OFF_QH + off) = h;
    *(uint2 *)(smc + OFF_QL + off) = l;
  }
  __syncthreads();

  // ldmatrix lane pattern
  const int lrow = lid & 15;
  const int lcol16 = (lid >> 4) << 4;  // 0 or 16 bytes

  // ---- preload Q A-fragments (persist across all 32 tiles) ----
  uint32_t qh[4][4], ql[4][4];
#pragma unroll
  for (int kc = 0; kc < 4; kc++) {
    uint32_t aoff = swz((uint32_t)((wrow + lrow) * 128 + kc * 32 + lcol16));
    ldsm4(qh[kc], sb + OFF_QH + aoff);
    ldsm4(ql[kc], sb + OFF_QL + aoff);
  }

  float O[8][4];
#pragma unroll
  for (int i = 0; i < 8; i++)
#pragma unroll
    for (int j = 0; j < 4; j++) O[i][j] = 0.f;
  float rs0 = 0.f, rs1 = 0.f;

  const int prow = wrow + (lid >> 2);

  for (int kt = 0; kt < NTILES; kt++) {
    __syncthreads();  // prior tile's K/V reads done

    // ---- K tile split (rows=key, 128B bf16 rows) ----
    const float *Ktg = Kg + (size_t)kt * TK * kD;
    for (int f = tid; f < TK * 16; f += NT) {
      int row = f >> 4, c4 = (f & 15) << 2;
      float4 x = *(const float4 *)&Ktg[row * kD + c4];
      uint2 h, l;
      splitpair(x.x, x.y, h.x, l.x);
      splitpair(x.z, x.w, h.y, l.y);
      uint32_t off = swz((uint32_t)(row * 128 + c4 * 2));
      *(uint2 *)(smc + OFF_KH + off) = h;
      *(uint2 *)(smc + OFF_KL + off) = l;
    }
    // ---- V tile split, natural [key][d] ----
    const float *Vtg = Vg + (size_t)kt * TK * kD;
    for (int f = tid; f < TK * 16; f += NT) {
      int row = f >> 4, c4 = (f & 15) << 2;
      float4 x = *(const float4 *)&Vtg[row * kD + c4];
      uint2 h, l;
      splitpair(x.x, x.y, h.x, l.x);
      splitpair(x.z, x.w, h.y, l.y);
      uint32_t off = swz((uint32_t)(row * 128 + c4 * 2));
      *(uint2 *)(smc + OFF_VH + off) = h;
      *(uint2 *)(smc + OFF_VL + off) = l;
    }
    // ---- mask ballots ----
    {
      int mv = (tid < TK) ? Mg[kt * TK + tid] : 0;
      uint32_t w = __ballot_sync(0xffffffffu, mv != 0);
      if (lid == 0 && wid < 2) ((uint32_t *)(smc + OFF_MASK))[wid] = w;
    }
    __syncthreads();

    // ---- QK^T: acc[8 n-tiles][4] ----
    float acc[8][4];
#pragma unroll
    for (int i = 0; i < 8; i++)
#pragma unroll
      for (int j = 0; j < 4; j++) acc[i][j] = 0.f;

#pragma unroll
    for (int kc = 0; kc < 4; kc++) {
#pragma unroll
      for (int ng = 0; ng < 4; ng++) {
        uint32_t bh4[4], bl4[4];
        uint32_t boff =
            swz((uint32_t)((ng * 16 + lrow) * 128 + kc * 32 + lcol16));
        ldsm4(bh4, sb + OFF_KH + boff);
        ldsm4(bl4, sb + OFF_KL + boff);
        mma16816(acc[ng * 2],     qh[kc], bh4[0], bh4[2]);
        mma16816(acc[ng * 2 + 1], qh[kc], bh4[1], bh4[3]);
        mma16816(acc[ng * 2],     qh[kc], bl4[0], bl4[2]);
        mma16816(acc[ng * 2 + 1], qh[kc], bl4[1], bl4[3]);
        mma16816(acc[ng * 2],     ql[kc], bh4[0], bh4[2]);
        mma16816(acc[ng * 2 + 1], ql[kc], bh4[1], bh4[3]);
      }
    }

    // ---- epilogue: mask + exp + rowsum; attn STG from regs ----
    const uint32_t mw0 = ((const uint32_t *)(smc + OFF_MASK))[0];
    const uint32_t mw1 = ((const uint32_t *)(smc + OFF_MASK))[1];
    float e[8][4];
#pragma unroll
    for (int nt = 0; nt < 8; nt++) {
      int c0 = nt * 8 + (lid & 3) * 2;
      uint32_t mword = (c0 < 32) ? mw0 : mw1;
      int bit = c0 & 31;
      bool m0 = (mword >> bit) & 1u, m1 = (mword >> (bit + 1)) & 1u;
      e[nt][0] = m0 ? __expf(acc[nt][0]) : 0.f;
      e[nt][1] = m1 ? __expf(acc[nt][1]) : 0.f;
      e[nt][2] = m0 ? __expf(acc[nt][2]) : 0.f;
      e[nt][3] = m1 ? __expf(acc[nt][3]) : 0.f;
      rs0 += e[nt][0] + e[nt][1];
      rs1 += e[nt][2] + e[nt][3];
      float2 w0 = {e[nt][0], e[nt][1]};
      float2 w1 = {e[nt][2], e[nt][3]};
      *(float2 *)&Ag[(size_t)prow * kS + kt * TK + c0] = w0;
      *(float2 *)&Ag[(size_t)(prow + 8) * kS + kt * TK + c0] = w1;
    }

    // ---- build PV A-fragments directly from e (C-frag == A-frag map) ----
    uint32_t ph[4][4], pl[4][4];
#pragma unroll
    for (int kc = 0; kc < 4; kc++) {
      splitpair(e[2 * kc][0],     e[2 * kc][1],     ph[kc][0], pl[kc][0]);
      splitpair(e[2 * kc][2],     e[2 * kc][3],     ph[kc][1], pl[kc][1]);
      splitpair(e[2 * kc + 1][0], e[2 * kc + 1][1], ph[kc][2], pl[kc][2]);
      splitpair(e[2 * kc + 1][2], e[2 * kc + 1][3], ph[kc][3], pl[kc][3]);
    }

    // ---- PV: O += P * V, B-frags via ldmatrix.trans on V[key][d] ----
#pragma unroll
    for (int kc = 0; kc < 4; kc++) {
#pragma unroll
      for (int ng = 0; ng < 4; ng++) {
        uint32_t vh4[4], vl4[4];
        uint32_t boff =
            swz((uint32_t)((kc * 16 + lrow) * 128 + ng * 32 + lcol16));
        ldsm4t(vh4, sb + OFF_VH + boff);
        ldsm4t(vl4, sb + OFF_VL + boff);
        mma16816(O[ng * 2],     ph[kc], vh4[0], vh4[1]);
        mma16816(O[ng * 2 + 1], ph[kc], vh4[2], vh4[3]);
        mma16816(O[ng * 2],     ph[kc], vl4[0], vl4[1]);
        mma16816(O[ng * 2 + 1], ph[kc], vl4[2], vl4[3]);
        mma16816(O[ng * 2],     pl[kc], vh4[0], vh4[1]);
        mma16816(O[ng * 2 + 1], pl[kc], vh4[2], vh4[3]);
      }
    }
  }

  // ---- finalize: quad-reduce rowsums, write O, stash inv ----
  rs0 += __shfl_xor_sync(0xffffffffu, rs0, 1);
  rs0 += __shfl_xor_sync(0xffffffffu, rs0, 2);
  rs1 += __shfl_xor_sync(0xffffffffu, rs1, 1);
  rs1 += __shfl_xor_sync(0xffffffffu, rs1, 2);
  float inv0 = 1.0f / rs0, inv1 = 1.0f / rs1;
  if ((lid & 3) == 0) {
    ((float *)(smc + OFF_INV))[prow] = inv0;
    ((float *)(smc + OFF_INV))[prow + 8] = inv1;
  }
#pragma unroll
  for (int nt = 0; nt < 8; nt++) {
    int col = nt * 8 + (lid & 3) * 2;
    float2 w0 = {O[nt][0] * inv0, O[nt][1] * inv0};
    float2 w1 = {O[nt][2] * inv1, O[nt][3] * inv1};
    *(float2 *)&Og[(size_t)prow * kD + col] = w0;
    *(float2 *)&Og[(size_t)(prow + 8) * kD + col] = w1;
  }
  __syncthreads();

  // ---- phase 2: rescale this block's attn rows (L2-hot) ----
  const float *invS = (const float *)(smc + OFF_INV);
#pragma unroll 1
  for (int f = tid; f < TQ * (kS / 4); f += NT) {
    int row = f >> 9;
    int c4 = (f & 511) << 2;
    float4 p = *(float4 *)&Ag[(size_t)row * kS + c4];
    float iv = invS[row];
    p.x *= iv; p.y *= iv; p.z *= iv; p.w *= iv;
    *(float4 *)&Ag[(size_t)row * kS + c4] = p;
  }
}

extern "C" void kernel_launch(void *const *d_in, const int *in_sizes, int n_in,
                              void *d_out, int out_size) {
  const float *q = (const float *)d_in[0];
  const float *k = (const float *)d_in[1];
  const float *v = (const float *)d_in[2];
  const int *m = (const int *)d_in[3];
  float *out = (float *)d_out;

  cudaFuncSetAttribute(sdpa_hmma2, cudaFuncAttributeMaxDynamicSharedMemorySize,
                       SMEM_BYTES);
  dim3 grid(kS / TQ, 64);  // (32, 64)
  sdpa_hmma2<<<grid, NT, SMEM_BYTES>>>(q, k, v, m, out);
}

// round 7
// speedup vs baseline: 2.3713x; 1.1581x over previous
#include <cuda_runtime.h>
#include <cuda_bf16.h>
#include <stdint.h>

namespace {

constexpr int kS = 2048, kD = 64;
constexpr long long OUT_ELEMS = 64LL * 2048 * 64;  // attn follows output
constexpr int TQ = 64, TK = 64, NT = 128, NTILES = kS / TK;
constexpr float SCALE = 0.125f;

// smem byte offsets
constexpr int OFF_INV     = 0;      // 64 floats
constexpr int OFF_MASKALL = 256;    // 64 u32 (2 per tile)
constexpr int OFF_KH = 512;         // bf16 hi K (also Q hi in prologue)
constexpr int OFF_KL = OFF_KH + 8192;
constexpr int OFF_VH = OFF_KL + 8192;   // V[key][d] natural
constexpr int OFF_VL = OFF_VH + 8192;
constexpr int OFF_SK = OFF_VL + 8192;   // fp32 staging K (16KB) / Q in prologue
constexpr int OFF_SV = OFF_SK + 16384;  // fp32 staging V (16KB)
constexpr int SMEM_BYTES = OFF_SV + 16384;  // 66304

__device__ __forceinline__ uint32_t swz(uint32_t off) {
  return off ^ ((off >> 3) & 0x70);
}
__device__ __forceinline__ uint32_t s2u(const void *p) {
  uint32_t a;
  asm("{ .reg .u64 t; cvta.to.shared.u64 t, %1; cvt.u32.u64 %0, t; }"
      : "=r"(a) : "l"(p));
  return a;
}
__device__ __forceinline__ void cpasync16(uint32_t saddr, const void *gaddr) {
  asm volatile("cp.async.cg.shared.global [%0], [%1], 16;" :: "r"(saddr),
               "l"(gaddr));
}
__device__ __forceinline__ void cpcommit() {
  asm volatile("cp.async.commit_group;" ::: "memory");
}
__device__ __forceinline__ void cpwait0() {
  asm volatile("cp.async.wait_group 0;" ::: "memory");
}
// pack (lo, hi) floats -> bf16x2 (lo in low 16 bits)
__device__ __forceinline__ uint32_t pkbf(float lo, float hi) {
  uint32_t r;
  asm("cvt.rn.bf16x2.f32 %0, %1, %2;" : "=r"(r) : "f"(hi), "f"(lo));
  return r;
}
// split (a,b) -> hi bf16x2 + residual bf16x2
__device__ __forceinline__ void splitpair(float a, float b, uint32_t &h,
                                          uint32_t &l) {
  float ah = __bfloat162float(__float2bfloat16(a));
  float bh = __bfloat162float(__float2bfloat16(b));
  h = pkbf(ah, bh);
  l = pkbf(a - ah, b - bh);
}
__device__ __forceinline__ void ldsm4(uint32_t *r, uint32_t addr) {
  asm volatile(
      "ldmatrix.sync.aligned.m8n8.x4.shared.b16 {%0,%1,%2,%3}, [%4];"
      : "=r"(r[0]), "=r"(r[1]), "=r"(r[2]), "=r"(r[3]) : "r"(addr));
}
__device__ __forceinline__ void ldsm4t(uint32_t *r, uint32_t addr) {
  asm volatile(
      "ldmatrix.sync.aligned.m8n8.x4.trans.shared.b16 {%0,%1,%2,%3}, [%4];"
      : "=r"(r[0]), "=r"(r[1]), "=r"(r[2]), "=r"(r[3]) : "r"(addr));
}
__device__ __forceinline__ void mma16816(float *d, const uint32_t *a,
                                         uint32_t b0, uint32_t b1) {
  asm volatile(
      "mma.sync.aligned.m16n8k16.row.col.f32.bf16.bf16.f32 "
      "{%0,%1,%2,%3}, {%4,%5,%6,%7}, {%8,%9}, {%0,%1,%2,%3};"
      : "+f"(d[0]), "+f"(d[1]), "+f"(d[2]), "+f"(d[3])
      : "r"(a[0]), "r"(a[1]), "r"(a[2]), "r"(a[3]), "r"(b0), "r"(b1));
}

}  // namespace

extern "C" __global__ void __launch_bounds__(NT, 3)
sdpa_hmma3(const float *__restrict__ Q, const float *__restrict__ K,
           const float *__restrict__ V, const int *__restrict__ M,
           float *__restrict__ Out) {
  extern __shared__ char smc[];
  const uint32_t sb = s2u(smc);
  const int tid = threadIdx.x;
  const int wid = tid >> 5, lid = tid & 31;
  const int wrow = wid * 16;
  const int bh = blockIdx.y, q0 = blockIdx.x * TQ;

  const float *Qg = Q + ((size_t)bh * kS + q0) * kD;
  const float *Kg = K + (size_t)bh * kS * kD;
  const float *Vg = V + (size_t)bh * kS * kD;
  const int *Mg = M + (size_t)bh * kS;
  float *Og = Out + ((size_t)bh * kS + q0) * kD;
  float *Ag = Out + OUT_ELEMS + ((size_t)bh * kS + q0) * (size_t)kS;

  // ---- prologue: stage Q fp32 via cp.async ----
#pragma unroll
  for (int i = 0; i < 8; i++) {
    int f = tid + i * NT;  // 1024 x 16B = 16KB
    cpasync16(sb + OFF_SK + f * 16, (const char *)Qg + f * 16);
  }
  cpcommit();
  cpwait0();
  __syncthreads();

  // convert Q -> bf16 (scaled, split) into KH/KL area temporarily
#pragma unroll
  for (int i = 0; i < 8; i++) {
    int f = tid + i * NT;
    int row = f >> 4, c4 = (f & 15) << 2;
    float4 x = *(const float4 *)(smc + OFF_SK + f * 16);
    x.x *= SCALE; x.y *= SCALE; x.z *= SCALE; x.w *= SCALE;
    uint2 h, l;
    splitpair(x.x, x.y, h.x, l.x);
    splitpair(x.z, x.w, h.y, l.y);
    uint32_t off = swz((uint32_t)(row * 128 + c4 * 2));
    *(uint2 *)(smc + OFF_KH + off) = h;
    *(uint2 *)(smc + OFF_KL + off) = l;
  }
  __syncthreads();

  // ldmatrix lane pattern
  const int lrow = lid & 15;
  const int lcol16 = (lid >> 4) << 4;

  // ---- preload Q A-fragments (persist across all tiles) ----
  uint32_t qh[4][4], ql[4][4];
#pragma unroll
  for (int kc = 0; kc < 4; kc++) {
    uint32_t aoff = swz((uint32_t)((wrow + lrow) * 128 + kc * 32 + lcol16));
    ldsm4(qh[kc], sb + OFF_KH + aoff);
    ldsm4(ql[kc], sb + OFF_KL + aoff);
  }

  // ---- all mask ballots (64 words) into smem ----
  {
    uint32_t *MW = (uint32_t *)(smc + OFF_MASKALL);
#pragma unroll 1
    for (int w = wid; w < 64; w += 4) {
      int mv = Mg[w * 32 + lid];
      uint32_t b = __ballot_sync(0xffffffffu, mv != 0);
      if (lid == 0) MW[w] = b;
    }
  }

  // ---- kick off tile 0 K/V staging ----
#pragma unroll
  for (int i = 0; i < 8; i++) {
    int f = tid + i * NT;
    cpasync16(sb + OFF_SK + f * 16, (const char *)Kg + f * 16);
    cpasync16(sb + OFF_SV + f * 16, (const char *)Vg + f * 16);
  }
  cpcommit();

  float O[8][4];
#pragma unroll
  for (int i = 0; i < 8; i++)
#pragma unroll
    for (int j = 0; j < 4; j++) O[i][j] = 0.f;
  float rs0 = 0.f, rs1 = 0.f;
  const int prow = wrow + (lid >> 2);

  for (int kt = 0; kt < NTILES; kt++) {
    cpwait0();
    __syncthreads();  // staging ready; prev tile's bf16 reads + Q ldsm done

    // ---- convert staging fp32 -> bf16 split buffers ----
#pragma unroll
    for (int i = 0; i < 8; i++) {
      int f = tid + i * NT;
      int row = f >> 4, c4 = (f & 15) << 2;
      uint32_t off = swz((uint32_t)(row * 128 + c4 * 2));
      float4 x = *(const float4 *)(smc + OFF_SK + f * 16);
      uint2 h, l;
      splitpair(x.x, x.y, h.x, l.x);
      splitpair(x.z, x.w, h.y, l.y);
      *(uint2 *)(smc + OFF_KH + off) = h;
      *(uint2 *)(smc + OFF_KL + off) = l;
      float4 y = *(const float4 *)(smc + OFF_SV + f * 16);
      uint2 vh, vl;
      splitpair(y.x, y.y, vh.x, vl.x);
      splitpair(y.z, y.w, vh.y, vl.y);
      *(uint2 *)(smc + OFF_VH + off) = vh;
      *(uint2 *)(smc + OFF_VL + off) = vl;
    }
    __syncthreads();

    // ---- prefetch next tile's K/V into staging ----
    if (kt + 1 < NTILES) {
      const char *Kn = (const char *)(Kg + (size_t)(kt + 1) * TK * kD);
      const char *Vn = (const char *)(Vg + (size_t)(kt + 1) * TK * kD);
#pragma unroll
      for (int i = 0; i < 8; i++) {
        int f = tid + i * NT;
        cpasync16(sb + OFF_SK + f * 16, Kn + f * 16);
        cpasync16(sb + OFF_SV + f * 16, Vn + f * 16);
      }
      cpcommit();
    }

    // ---- QK^T ----
    float acc[8][4];
#pragma unroll
    for (int i = 0; i < 8; i++)
#pragma unroll
      for (int j = 0; j < 4; j++) acc[i][j] = 0.f;

#pragma unroll
    for (int kc = 0; kc < 4; kc++) {
#pragma unroll
      for (int ng = 0; ng < 4; ng++) {
        uint32_t bh4[4], bl4[4];
        uint32_t boff =
            swz((uint32_t)((ng * 16 + lrow) * 128 + kc * 32 + lcol16));
        ldsm4(bh4, sb + OFF_KH + boff);
        ldsm4(bl4, sb + OFF_KL + boff);
        mma16816(acc[ng * 2],     qh[kc], bh4[0], bh4[2]);
        mma16816(acc[ng * 2 + 1], qh[kc], bh4[1], bh4[3]);
        mma16816(acc[ng * 2],     qh[kc], bl4[0], bl4[2]);
        mma16816(acc[ng * 2 + 1], qh[kc], bl4[1], bl4[3]);
        mma16816(acc[ng * 2],     ql[kc], bh4[0], bh4[2]);
        mma16816(acc[ng * 2 + 1], ql[kc], bh4[1], bh4[3]);
      }
    }

    // ---- epilogue: mask + exp + rowsum; attn STG from regs ----
    const uint32_t mw0 = ((const uint32_t *)(smc + OFF_MASKALL))[kt * 2];
    const uint32_t mw1 = ((const uint32_t *)(smc + OFF_MASKALL))[kt * 2 + 1];
    float e[8][4];
#pragma unroll
    for (int nt = 0; nt < 8; nt++) {
      int c0 = nt * 8 + (lid & 3) * 2;
      uint32_t mword = (c0 < 32) ? mw0 : mw1;
      int bit = c0 & 31;
      bool m0 = (mword >> bit) & 1u, m1 = (mword >> (bit + 1)) & 1u;
      e[nt][0] = m0 ? __expf(acc[nt][0]) : 0.f;
      e[nt][1] = m1 ? __expf(acc[nt][1]) : 0.f;
      e[nt][2] = m0 ? __expf(acc[nt][2]) : 0.f;
      e[nt][3] = m1 ? __expf(acc[nt][3]) : 0.f;
      rs0 += e[nt][0] + e[nt][1];
      rs1 += e[nt][2] + e[nt][3];
      float2 w0 = {e[nt][0], e[nt][1]};
      float2 w1 = {e[nt][2], e[nt][3]};
      *(float2 *)&Ag[(size_t)prow * kS + kt * TK + c0] = w0;
      *(float2 *)&Ag[(size_t)(prow + 8) * kS + kt * TK + c0] = w1;
    }

    // ---- PV A-fragments from e (C-frag == A-frag map) ----
    uint32_t ph[4][4], pl[4][4];
#pragma unroll
    for (int kc = 0; kc < 4; kc++) {
      splitpair(e[2 * kc][0],     e[2 * kc][1],     ph[kc][0], pl[kc][0]);
      splitpair(e[2 * kc][2],     e[2 * kc][3],     ph[kc][1], pl[kc][1]);
      splitpair(e[2 * kc + 1][0], e[2 * kc + 1][1], ph[kc][2], pl[kc][2]);
      splitpair(e[2 * kc + 1][2], e[2 * kc + 1][3], ph[kc][3], pl[kc][3]);
    }

    // ---- PV: O += P * V ----
#pragma unroll
    for (int kc = 0; kc < 4; kc++) {
#pragma unroll
      for (int ng = 0; ng < 4; ng++) {
        uint32_t vh4[4], vl4[4];
        uint32_t boff =
            swz((uint32_t)((kc * 16 + lrow) * 128 + ng * 32 + lcol16));
        ldsm4t(vh4, sb + OFF_VH + boff);
        ldsm4t(vl4, sb + OFF_VL + boff);
        mma16816(O[ng * 2],     ph[kc], vh4[0], vh4[1]);
        mma16816(O[ng * 2 + 1], ph[kc], vh4[2], vh4[3]);
        mma16816(O[ng * 2],     ph[kc], vl4[0], vl4[1]);
        mma16816(O[ng * 2 + 1], ph[kc], vl4[2], vl4[3]);
        mma16816(O[ng * 2],     pl[kc], vh4[0], vh4[1]);
        mma16816(O[ng * 2 + 1], pl[kc], vh4[2], vh4[3]);
      }
    }
  }

  // ---- finalize ----
  rs0 += __shfl_xor_sync(0xffffffffu, rs0, 1);
  rs0 += __shfl_xor_sync(0xffffffffu, rs0, 2);
  rs1 += __shfl_xor_sync(0xffffffffu, rs1, 1);
  rs1 += __shfl_xor_sync(0xffffffffu, rs1, 2);
  float inv0 = 1.0f / rs0, inv1 = 1.0f / rs1;
  if ((lid & 3) == 0) {
    ((float *)(smc + OFF_INV))[prow] = inv0;
    ((float *)(smc + OFF_INV))[prow + 8] = inv1;
  }
#pragma unroll
  for (int nt = 0; nt < 8; nt++) {
    int col = nt * 8 + (lid & 3) * 2;
    float2 w0 = {O[nt][0] * inv0, O[nt][1] * inv0};
    float2 w1 = {O[nt][2] * inv1, O[nt][3] * inv1};
    *(float2 *)&Og[(size_t)prow * kD + col] = w0;
    *(float2 *)&Og[(size_t)(prow + 8) * kD + col] = w1;
  }
  __syncthreads();

  // ---- phase 2: rescale this block's attn rows (L2-hot) ----
  const float *invS = (const float *)(smc + OFF_INV);
#pragma unroll 1
  for (int f = tid; f < TQ * (kS / 4); f += NT) {
    int row = f >> 9;
    int c4 = (f & 511) << 2;
    float4 p = *(float4 *)&Ag[(size_t)row * kS + c4];
    float iv = invS[row];
    p.x *= iv; p.y *= iv; p.z *= iv; p.w *= iv;
    *(float4 *)&Ag[(size_t)row * kS + c4] = p;
  }
}

extern "C" void kernel_launch(void *const *d_in, const int *in_sizes, int n_in,
                              void *d_out, int out_size) {
  const float *q = (const float *)d_in[0];
  const float *k = (const float *)d_in[1];
  const float *v = (const float *)d_in[2];
  const int *m = (const int *)d_in[3];
  float *out = (float *)d_out;

  cudaFuncSetAttribute(sdpa_hmma3, cudaFuncAttributeMaxDynamicSharedMemorySize,
                       SMEM_BYTES);
  dim3 grid(kS / TQ, 64);  // (32, 64)
  sdpa_hmma3<<<grid, NT, SMEM_BYTES>>>(q, k, v, m, out);
}